// round 14
// baseline (speedup 1.0000x reference)
#include <cuda_runtime.h>
#include <cuda_fp16.h>
#include <stdint.h>

namespace {
constexpr int kB = 64, kSQ = 1024, kSK = 1024, kD = 256, kDV = 256;
constexpr int BQ = 64, BKC = 64, NCH = kSK / BKC, NT = 256;
constexpr float kDropP = 0.1f, kKeepInv = 1.0f / 0.9f;
constexpr float kQScale = 0.0625f * 1.44269504088896f;  // fold log2e: exp(s)=exp2(s')

constexpr uint32_t SM_Q = 0;        // 64 x 512B = 32KB
constexpr uint32_t SM_K = 32768;    // 64 x 512B = 32KB (single buffer)
constexpr uint32_t SM_V = 65536;    // 64 x 512B = 32KB (single buffer)
constexpr uint32_t SM_P = 98304;    // 64 rows x 128B = 8KB
constexpr uint32_t SM_L = 106496;   // float[2][64] = 512B
constexpr uint32_t SM_BYTES = 107008 + 1024;  // ~105.5KB -> 2 CTAs/SM

__device__ __forceinline__ uint32_t swz(int row, int g) {  // 512B rows
  return (uint32_t)(row * 512 + ((g ^ (row & 7)) << 4));
}
__device__ __forceinline__ void cpa16(uint32_t d, const void* s) {
  asm volatile("cp.async.cg.shared.global [%0], [%1], 16;" :: "r"(d), "l"(s));
}
__device__ __forceinline__ void cp_commit() { asm volatile("cp.async.commit_group;" ::: "memory"); }
__device__ __forceinline__ void cp_wait1() { asm volatile("cp.async.wait_group 1;" ::: "memory"); }
__device__ __forceinline__ void cp_wait0() { asm volatile("cp.async.wait_group 0;" ::: "memory"); }

__device__ __forceinline__ float ex2(float x) {
  float r;
  asm("ex2.approx.f32 %0, %1;" : "=f"(r) : "f"(x));
  return r;
}
__device__ __forceinline__ void ldsm4(uint32_t* r, uint32_t a) {
  asm volatile("ldmatrix.sync.aligned.m8n8.x4.shared.b16 {%0,%1,%2,%3}, [%4];"
               : "=r"(r[0]), "=r"(r[1]), "=r"(r[2]), "=r"(r[3]) : "r"(a));
}
__device__ __forceinline__ void ldsm4t(uint32_t* r, uint32_t a) {
  asm volatile("ldmatrix.sync.aligned.m8n8.x4.trans.shared.b16 {%0,%1,%2,%3}, [%4];"
               : "=r"(r[0]), "=r"(r[1]), "=r"(r[2]), "=r"(r[3]) : "r"(a));
}
__device__ __forceinline__ void mma16816(float* d, const uint32_t* a, const uint32_t* b) {
  asm volatile(
      "mma.sync.aligned.m16n8k16.row.col.f32.f16.f16.f32 "
      "{%0,%1,%2,%3}, {%4,%5,%6,%7}, {%8,%9}, {%0,%1,%2,%3};"
      : "+f"(d[0]), "+f"(d[1]), "+f"(d[2]), "+f"(d[3])
      : "r"(a[0]), "r"(a[1]), "r"(a[2]), "r"(a[3]), "r"(b[0]), "r"(b[1]));
}
}  // namespace

__device__ __half g_Kh[(size_t)kB * kSK * kD];
__device__ __half g_Vh[(size_t)kB * kSK * kDV];
__device__ uint32_t g_dropbits[(size_t)kB * kSQ * (kSK / 32)];  // 8MB
__device__ uint32_t g_maskbits[kB * (kSK / 32)];                // 8KB

__global__ void prep_fused(const float* __restrict__ k, const float* __restrict__ v,
                           const float* __restrict__ du, const int* __restrict__ mask) {
  constexpr int nConv = (int)((size_t)kB * kSK * kD / 8 / 256);    // 8192
  constexpr int nDrop = (int)((size_t)kB * kSQ * kSK / 1024 / 8);  // 8192
  const int bx = blockIdx.x;
  if (bx < nConv) {
    const size_t base = ((size_t)bx * 256 + threadIdx.x) * 8;
    {
      float4 x0 = *reinterpret_cast<const float4*>(k + base);
      float4 x1 = *reinterpret_cast<const float4*>(k + base + 4);
      __half2* o = reinterpret_cast<__half2*>(g_Kh + base);
      o[0] = __floats2half2_rn(x0.x, x0.y);
      o[1] = __floats2half2_rn(x0.z, x0.w);
      o[2] = __floats2half2_rn(x1.x, x1.y);
      o[3] = __floats2half2_rn(x1.z, x1.w);
    }
    {
      float4 x0 = *reinterpret_cast<const float4*>(v + base);
      float4 x1 = *reinterpret_cast<const float4*>(v + base + 4);
      __half2* o = reinterpret_cast<__half2*>(g_Vh + base);
      o[0] = __floats2half2_rn(x0.x, x0.y);
      o[1] = __floats2half2_rn(x0.z, x0.w);
      o[2] = __floats2half2_rn(x1.x, x1.y);
      o[3] = __floats2half2_rn(x1.z, x1.w);
    }
  } else if (bx < nConv + nDrop) {
    const int lane = threadIdx.x & 31;
    const size_t warp = (((size_t)(bx - nConv) * 256) + threadIdx.x) >> 5;
    const size_t base = warp * 1024;
    uint32_t myword = 0;
#pragma unroll
    for (int i = 0; i < 32; i++) {
      const float u = du[base + (size_t)i * 32 + lane];
      const uint32_t bm = __ballot_sync(0xffffffffu, u >= kDropP);
      if (lane == i) myword = bm;
    }
    g_dropbits[warp * 32 + lane] = myword;
  } else {
    const int lane = threadIdx.x & 31;
    const int warp = (int)((((bx - nConv - nDrop) * 256) + threadIdx.x) >> 5);
    const size_t base = (size_t)warp * 1024;
    uint32_t myword = 0;
#pragma unroll
    for (int i = 0; i < 32; i++) {
      const int m = mask[base + (size_t)i * 32 + lane];
      const uint32_t bm = __ballot_sync(0xffffffffu, m != 0);
      if (lane == i) myword = bm;
    }
    g_maskbits[warp * 32 + lane] = myword;
  }
}

__global__ __launch_bounds__(NT, 2)
void attn_hmma_kernel(const float* __restrict__ q, float* __restrict__ out) {
  extern __shared__ char smraw[];
  uint32_t smb = (uint32_t)__cvta_generic_to_shared(smraw);
  smb = (smb + 1023u) & ~1023u;
  const int tid = threadIdx.x, wid = tid >> 5, lane = tid & 31;
  const int b = blockIdx.y, q0 = blockIdx.x * BQ;
  const int g = wid & 3;    // QK row group (16 rows)
  const int kh = wid >> 2;  // QK key half (32 keys)
  const int pr = wid >> 2;  // PV row group (32 rows)
  const int pg = wid & 3;   // PV col group (64 cols)

  auto load_k = [&](int c) {
#pragma unroll
    for (int u = 0; u < 8; u++) {
      const int idx = tid + u * NT, row = idx >> 5, gr = idx & 31;
      cpa16(smb + SM_K + swz(row, gr),
            g_Kh + ((size_t)(b * kSK + c * BKC + row)) * kD + gr * 8);
    }
  };
  auto load_v = [&](int c) {
#pragma unroll
    for (int u = 0; u < 8; u++) {
      const int idx = tid + u * NT, row = idx >> 5, gr = idx & 31;
      cpa16(smb + SM_V + swz(row, gr),
            g_Vh + ((size_t)(b * kSK + c * BKC + row)) * kDV + gr * 8);
    }
  };

  load_k(0); cp_commit();  // G: K0
  load_v(0); cp_commit();  // G: V0

  // ---- prologue: Q fp32 -> fp16 * (2^-4 * log2e) into swizzled SM_Q ----
#pragma unroll
  for (int u = 0; u < 8; u++) {
    const int idx = tid + u * NT, row = idx >> 5, gr = idx & 31;
    const float* src = q + ((size_t)(b * kSQ + q0 + row)) * kD + gr * 8;
    const float4 x0 = *reinterpret_cast<const float4*>(src);
    const float4 x1 = *reinterpret_cast<const float4*>(src + 4);
    __half2 h0 = __floats2half2_rn(x0.x * kQScale, x0.y * kQScale);
    __half2 h1 = __floats2half2_rn(x0.z * kQScale, x0.w * kQScale);
    __half2 h2 = __floats2half2_rn(x1.x * kQScale, x1.y * kQScale);
    __half2 h3 = __floats2half2_rn(x1.z * kQScale, x1.w * kQScale);
    asm volatile("st.shared.v4.b32 [%0], {%1,%2,%3,%4};"
                 :: "r"(smb + SM_Q + swz(row, gr)),
                    "r"(*reinterpret_cast<uint32_t*>(&h0)), "r"(*reinterpret_cast<uint32_t*>(&h1)),
                    "r"(*reinterpret_cast<uint32_t*>(&h2)), "r"(*reinterpret_cast<uint32_t*>(&h3))
                 : "memory");
  }

  // ---- lane constants ----
  const int lq = lane & 15, lhalf = lane >> 4;
  const uint32_t x7s = (uint32_t)((lq & 7) << 4);    // pre-shifted swizzle consts
  const uint32_t x7ks = (uint32_t)((lane & 7) << 4);
  const int rowa = lane >> 2, colq = (lane & 3) * 2;
  const int r0l = g * 16 + rowa;
  const uint32_t qbase = smb + SM_Q + (g * 16 + lq) * 512;
  const int krow_off = (lane & 7) + ((lane >> 4) << 3);
  const int kg_half = (lane >> 3) & 1;
  const uint32_t pb0 = smb + SM_P + (pr * 32 + lq) * 128;
  const uint32_t pb1 = pb0 + 16 * 128;
  uint32_t voff[4];
#pragma unroll
  for (int nt = 0; nt < 4; nt++)
    voff[nt] = ((uint32_t)((pg * 8 + nt * 2 + lhalf) << 4)) ^ x7s;
  const uint32_t pst0 = smb + SM_P + r0l * 128 + (lane & 3) * 4;
  const uint32_t pst1 = pst0 + 8 * 128;

  const int grow0 = q0 + r0l;

  float o[2][8][4];
#pragma unroll
  for (int mt = 0; mt < 2; mt++)
#pragma unroll
    for (int nt = 0; nt < 8; nt++)
#pragma unroll
      for (int e = 0; e < 4; e++) o[mt][nt][e] = 0.f;
  float lac0 = 0.f, lac1 = 0.f;

  for (int kt = 0; kt < NCH; kt++) {
    cp_wait1();       // K(kt) resident (V(kt) may still be in flight)
    __syncthreads();  // [S1] K visible; V-buf free (prev PV done)

    // hoisted bit-words (hidden under QK)
    const int wix = kt * 2 + kh;
    const uint32_t mword = g_maskbits[b * 32 + wix];
    const uint32_t dw0 = g_dropbits[(size_t)(b * kSQ + grow0) * 32 + wix];
    const uint32_t dw1 = g_dropbits[(size_t)(b * kSQ + grow0 + 8) * 32 + wix];

    // ---- QK: 16 rows x 32 keys per warp, k=256 ----
    float s[4][4];
#pragma unroll
    for (int t = 0; t < 4; t++) { s[t][0] = s[t][1] = s[t][2] = s[t][3] = 0.f; }

    const uint32_t kb0 = smb + SM_K + (kh * 32 + krow_off) * 512;
#pragma unroll
    for (int ds = 0; ds < 16; ds++) {
      uint32_t a[4], bb[8];
      ldsm4(a, qbase + (((uint32_t)(((ds << 1) + lhalf) << 4)) ^ x7s));
      const uint32_t bo = ((uint32_t)(((ds << 1) + kg_half) << 4)) ^ x7ks;
      ldsm4(bb, kb0 + bo);
      ldsm4(bb + 4, kb0 + 8192 + bo);
      mma16816(s[0], a, bb + 0);
      mma16816(s[1], a, bb + 2);
      mma16816(s[2], a, bb + 4);
      mma16816(s[3], a, bb + 6);
    }

    // ---- mask/exp2/dropout via bitwords; write P fp16 to smem ----
#pragma unroll
    for (int t = 0; t < 4; t++) {
      const int bp = t * 8 + colq;
      const bool m0 = (mword >> bp) & 1u, m1 = (mword >> (bp + 1)) & 1u;
      float p0 = m0 ? ex2(s[t][0]) : 0.f;
      float p1 = m1 ? ex2(s[t][1]) : 0.f;
      float p2 = m0 ? ex2(s[t][2]) : 0.f;
      float p3 = m1 ? ex2(s[t][3]) : 0.f;
      lac0 += p0 + p1;
      lac1 += p2 + p3;
      p0 *= ((dw0 >> bp) & 1u) ? kKeepInv : 0.f;
      p1 *= ((dw0 >> (bp + 1)) & 1u) ? kKeepInv : 0.f;
      p2 *= ((dw1 >> bp) & 1u) ? kKeepInv : 0.f;
      p3 *= ((dw1 >> (bp + 1)) & 1u) ? kKeepInv : 0.f;
      __half2 ha = __floats2half2_rn(p0, p1), hb = __floats2half2_rn(p2, p3);
      const int grp = kh * 4 + t;
      const uint32_t xo = (uint32_t)((grp ^ rowa) << 4);
      asm volatile("st.shared.b32 [%0], %1;" :: "r"(pst0 + xo), "r"(*reinterpret_cast<uint32_t*>(&ha)) : "memory");
      asm volatile("st.shared.b32 [%0], %1;" :: "r"(pst1 + xo), "r"(*reinterpret_cast<uint32_t*>(&hb)) : "memory");
    }

    cp_wait0();       // V(kt) resident (only V in flight here)
    __syncthreads();  // [S2] P + V visible; K consumed by all warps

    if (kt + 1 < NCH) { load_k(kt + 1); cp_commit(); }

    // ---- PV: 32 rows x 64 dv per warp ----
#pragma unroll
    for (int ks = 0; ks < 4; ks++) {
      uint32_t ap0[4], ap1[4];
      const uint32_t po = ((uint32_t)(((ks << 1) + lhalf) << 4)) ^ x7s;
      ldsm4(ap0, pb0 + po);
      ldsm4(ap1, pb1 + po);
      const uint32_t vb = smb + SM_V + (ks * 16 + lq) * 512;
#pragma unroll
      for (int nt = 0; nt < 4; nt++) {
        uint32_t bb[4];
        ldsm4t(bb, vb + voff[nt]);
        mma16816(o[0][nt * 2 + 0], ap0, bb + 0);
        mma16816(o[0][nt * 2 + 1], ap0, bb + 2);
        mma16816(o[1][nt * 2 + 0], ap1, bb + 0);
        mma16816(o[1][nt * 2 + 1], ap1, bb + 2);
      }
    }
    __syncthreads();  // [S3] V consumed

    if (kt + 1 < NCH) { load_v(kt + 1); cp_commit(); }  // in flight: K(kt+1), V(kt+1)
  }

  // ---- l combine across key halves via smem ----
  lac0 += __shfl_xor_sync(0xffffffffu, lac0, 1);
  lac0 += __shfl_xor_sync(0xffffffffu, lac0, 2);
  lac1 += __shfl_xor_sync(0xffffffffu, lac1, 1);
  lac1 += __shfl_xor_sync(0xffffffffu, lac1, 2);
  if ((lane & 3) == 0) {
    asm volatile("st.shared.f32 [%0], %1;" :: "r"(smb + SM_L + (kh * 64 + r0l) * 4), "f"(lac0) : "memory");
    asm volatile("st.shared.f32 [%0], %1;" :: "r"(smb + SM_L + (kh * 64 + r0l + 8) * 4), "f"(lac1) : "memory");
  }
  __syncthreads();

#pragma unroll
  for (int mt = 0; mt < 2; mt++) {
    const int lr0 = pr * 32 + mt * 16 + rowa;
    float la0, lb0, la1, lb1;
    asm volatile("ld.shared.f32 %0, [%1];" : "=f"(la0) : "r"(smb + SM_L + lr0 * 4));
    asm volatile("ld.shared.f32 %0, [%1];" : "=f"(lb0) : "r"(smb + SM_L + (64 + lr0) * 4));
    asm volatile("ld.shared.f32 %0, [%1];" : "=f"(la1) : "r"(smb + SM_L + (lr0 + 8) * 4));
    asm volatile("ld.shared.f32 %0, [%1];" : "=f"(lb1) : "r"(smb + SM_L + (64 + lr0 + 8) * 4));
    const float inv0 = 1.0f / (la0 + lb0), inv1 = 1.0f / (la1 + lb1);
    float* o0 = out + ((size_t)b * kSQ + q0 + lr0) * kDV + pg * 64;
    float* o1 = o0 + (size_t)8 * kDV;
#pragma unroll
    for (int nt = 0; nt < 8; nt++) {
      const int c = nt * 8 + colq;
      float2 w0, w1;
      w0.x = o[mt][nt][0] * inv0;
      w0.y = o[mt][nt][1] * inv0;
      w1.x = o[mt][nt][2] * inv1;
      w1.y = o[mt][nt][3] * inv1;
      *reinterpret_cast<float2*>(o0 + c) = w0;
      *reinterpret_cast<float2*>(o1 + c) = w1;
    }
  }
}

extern "C" void kernel_launch(void* const* d_in, const int* in_sizes, int n_in,
                              void* d_out, int out_size) {
  const float* q = (const float*)d_in[0];
  const float* k = (const float*)d_in[1];
  const float* v = (const float*)d_in[2];
  const int* mask = (const int*)d_in[3];
  const float* du = (const float*)d_in[4];
  float* out = (float*)d_out;

  constexpr int nConv = (int)((size_t)kB * kSK * kD / 8 / 256);
  constexpr int nDrop = (int)((size_t)kB * kSQ * kSK / 1024 / 8);
  prep_fused<<<nConv + nDrop + 8, 256>>>(k, v, du, mask);

  cudaFuncSetAttribute(attn_hmma_kernel, cudaFuncAttributeMaxDynamicSharedMemorySize,
                       (int)SM_BYTES);
  attn_hmma_kernel<<<dim3(kSQ / BQ, kB), NT, SM_BYTES>>>(q, out);
}

// round 15
// speedup vs baseline: 1.0199x; 1.0199x over previous
#include <cuda_runtime.h>
#include <cuda_fp16.h>
#include <stdint.h>

namespace {
constexpr int kB = 64, kSQ = 1024, kSK = 1024, kD = 256, kDV = 256;
constexpr int BQ = 64, BKC = 64, NCH = kSK / BKC, NT = 256;
constexpr float kDropP = 0.1f;
constexpr float kKeepInv = 1.0f / 0.9f;                  // folded into V in prep
constexpr float kQScale = 0.0625f * 1.44269504088896f;   // scale * log2e (exp -> exp2)

constexpr uint32_t SM_Q = 0;        // 64 x 512B = 32KB
constexpr uint32_t SM_K = 32768;    // 64 x 512B = 32KB (single buffer)
constexpr uint32_t SM_V = 65536;    // 64 x 512B = 32KB (single buffer)
constexpr uint32_t SM_P = 98304;    // 64 rows x 128B = 8KB
constexpr uint32_t SM_L = 106496;   // float[2][64] = 512B
constexpr uint32_t SM_BYTES = 107008 + 1024;  // ~105.5KB -> 2 CTAs/SM

__device__ __forceinline__ uint32_t swz(int row, int g) {  // 512B rows
  return (uint32_t)(row * 512 + ((g ^ (row & 7)) << 4));
}
__device__ __forceinline__ void cpa16(uint32_t d, const void* s) {
  asm volatile("cp.async.cg.shared.global [%0], [%1], 16;" :: "r"(d), "l"(s));
}
__device__ __forceinline__ void cp_commit() { asm volatile("cp.async.commit_group;" ::: "memory"); }
__device__ __forceinline__ void cp_wait1() { asm volatile("cp.async.wait_group 1;" ::: "memory"); }
__device__ __forceinline__ void cp_wait0() { asm volatile("cp.async.wait_group 0;" ::: "memory"); }

__device__ __forceinline__ float ex2(float x) {
  float r;
  asm("ex2.approx.f32 %0, %1;" : "=f"(r) : "f"(x));
  return r;
}
__device__ __forceinline__ void ldsm4(uint32_t* r, uint32_t a) {
  asm volatile("ldmatrix.sync.aligned.m8n8.x4.shared.b16 {%0,%1,%2,%3}, [%4];"
               : "=r"(r[0]), "=r"(r[1]), "=r"(r[2]), "=r"(r[3]) : "r"(a));
}
__device__ __forceinline__ void ldsm4t(uint32_t* r, uint32_t a) {
  asm volatile("ldmatrix.sync.aligned.m8n8.x4.trans.shared.b16 {%0,%1,%2,%3}, [%4];"
               : "=r"(r[0]), "=r"(r[1]), "=r"(r[2]), "=r"(r[3]) : "r"(a));
}
__device__ __forceinline__ void mma16816(float* d, const uint32_t* a, const uint32_t* b) {
  asm volatile(
      "mma.sync.aligned.m16n8k16.row.col.f32.f16.f16.f32 "
      "{%0,%1,%2,%3}, {%4,%5,%6,%7}, {%8,%9}, {%0,%1,%2,%3};"
      : "+f"(d[0]), "+f"(d[1]), "+f"(d[2]), "+f"(d[3])
      : "r"(a[0]), "r"(a[1]), "r"(a[2]), "r"(a[3]), "r"(b[0]), "r"(b[1]));
}
}  // namespace

__device__ __half g_Kh[(size_t)kB * kSK * kD];
__device__ __half g_Vh[(size_t)kB * kSK * kDV];   // V * keepinv
__device__ uint32_t g_dropbits[(size_t)kB * kSQ * (kSK / 32)];  // 8MB
__device__ uint32_t g_maskbits[kB * (kSK / 32)];                // 8KB

__global__ void prep_fused(const float* __restrict__ k, const float* __restrict__ v,
                           const float* __restrict__ du, const int* __restrict__ mask) {
  constexpr int nConv = (int)((size_t)kB * kSK * kD / 8 / 256);    // 8192
  constexpr int nDrop = (int)((size_t)kB * kSQ * kSK / 1024 / 8);  // 8192
  const int bx = blockIdx.x;
  if (bx < nConv) {
    const size_t base = ((size_t)bx * 256 + threadIdx.x) * 8;
    {
      float4 x0 = *reinterpret_cast<const float4*>(k + base);
      float4 x1 = *reinterpret_cast<const float4*>(k + base + 4);
      __half2* o = reinterpret_cast<__half2*>(g_Kh + base);
      o[0] = __floats2half2_rn(x0.x, x0.y);
      o[1] = __floats2half2_rn(x0.z, x0.w);
      o[2] = __floats2half2_rn(x1.x, x1.y);
      o[3] = __floats2half2_rn(x1.z, x1.w);
    }
    {
      float4 x0 = *reinterpret_cast<const float4*>(v + base);
      float4 x1 = *reinterpret_cast<const float4*>(v + base + 4);
      __half2* o = reinterpret_cast<__half2*>(g_Vh + base);
      o[0] = __floats2half2_rn(x0.x * kKeepInv, x0.y * kKeepInv);
      o[1] = __floats2half2_rn(x0.z * kKeepInv, x0.w * kKeepInv);
      o[2] = __floats2half2_rn(x1.x * kKeepInv, x1.y * kKeepInv);
      o[3] = __floats2half2_rn(x1.z * kKeepInv, x1.w * kKeepInv);
    }
  } else if (bx < nConv + nDrop) {
    const int lane = threadIdx.x & 31;
    const size_t warp = (((size_t)(bx - nConv) * 256) + threadIdx.x) >> 5;
    const size_t base = warp * 1024;
    uint32_t myword = 0;
#pragma unroll
    for (int i = 0; i < 32; i++) {
      const float u = du[base + (size_t)i * 32 + lane];
      const uint32_t bm = __ballot_sync(0xffffffffu, u >= kDropP);
      if (lane == i) myword = bm;
    }
    g_dropbits[warp * 32 + lane] = myword;
  } else {
    const int lane = threadIdx.x & 31;
    const int warp = (int)((((bx - nConv - nDrop) * 256) + threadIdx.x) >> 5);
    const size_t base = (size_t)warp * 1024;
    uint32_t myword = 0;
#pragma unroll
    for (int i = 0; i < 32; i++) {
      const int m = mask[base + (size_t)i * 32 + lane];
      const uint32_t bm = __ballot_sync(0xffffffffu, m != 0);
      if (lane == i) myword = bm;
    }
    g_maskbits[warp * 32 + lane] = myword;
  }
}

__global__ __launch_bounds__(NT, 2)
void attn_hmma_kernel(const float* __restrict__ q, float* __restrict__ out) {
  extern __shared__ char smraw[];
  uint32_t smb = (uint32_t)__cvta_generic_to_shared(smraw);
  smb = (smb + 1023u) & ~1023u;
  const int tid = threadIdx.x, wid = tid >> 5, lane = tid & 31;
  const int b = blockIdx.y, q0 = blockIdx.x * BQ;
  const int g = wid & 3;    // QK row group (16 rows)
  const int kh = wid >> 2;  // QK key half (32 keys)
  const int pr = wid >> 2;  // PV row group (32 rows)
  const int pg = wid & 3;   // PV col group (64 cols)

  auto load_k = [&](int c) {
#pragma unroll
    for (int u = 0; u < 8; u++) {
      const int idx = tid + u * NT, row = idx >> 5, gr = idx & 31;
      cpa16(smb + SM_K + swz(row, gr),
            g_Kh + ((size_t)(b * kSK + c * BKC + row)) * kD + gr * 8);
    }
  };
  auto load_v = [&](int c) {
#pragma unroll
    for (int u = 0; u < 8; u++) {
      const int idx = tid + u * NT, row = idx >> 5, gr = idx & 31;
      cpa16(smb + SM_V + swz(row, gr),
            g_Vh + ((size_t)(b * kSK + c * BKC + row)) * kDV + gr * 8);
    }
  };

  load_k(0); cp_commit();  // G: K0
  load_v(0); cp_commit();  // G: V0

  // ---- prologue: Q fp32 -> fp16 * (2^-4 * log2e) into swizzled SM_Q ----
#pragma unroll
  for (int u = 0; u < 8; u++) {
    const int idx = tid + u * NT, row = idx >> 5, gr = idx & 31;
    const float* src = q + ((size_t)(b * kSQ + q0 + row)) * kD + gr * 8;
    const float4 x0 = *reinterpret_cast<const float4*>(src);
    const float4 x1 = *reinterpret_cast<const float4*>(src + 4);
    __half2 h0 = __floats2half2_rn(x0.x * kQScale, x0.y * kQScale);
    __half2 h1 = __floats2half2_rn(x0.z * kQScale, x0.w * kQScale);
    __half2 h2 = __floats2half2_rn(x1.x * kQScale, x1.y * kQScale);
    __half2 h3 = __floats2half2_rn(x1.z * kQScale, x1.w * kQScale);
    asm volatile("st.shared.v4.b32 [%0], {%1,%2,%3,%4};"
                 :: "r"(smb + SM_Q + swz(row, gr)),
                    "r"(*reinterpret_cast<uint32_t*>(&h0)), "r"(*reinterpret_cast<uint32_t*>(&h1)),
                    "r"(*reinterpret_cast<uint32_t*>(&h2)), "r"(*reinterpret_cast<uint32_t*>(&h3))
                 : "memory");
  }

  // ---- lane constants (R13 forms) ----
  const int lq = lane & 15, lhalf = lane >> 4;
  const int x7 = lq & 7;
  const int x7k = lane & 7;
  const int rowa = lane >> 2, colq = (lane & 3) * 2;
  const int r0l = g * 16 + rowa;
  const uint32_t qbase = smb + SM_Q + (g * 16 + lq) * 512;
  const int krow_off = (lane & 7) + ((lane >> 4) << 3);
  const int kg_half = (lane >> 3) & 1;
  const uint32_t pb0 = smb + SM_P + (pr * 32 + lq) * 128;
  const uint32_t pb1 = pb0 + 16 * 128;
  uint32_t voff[4];
#pragma unroll
  for (int nt = 0; nt < 4; nt++) voff[nt] = (uint32_t)(((pg * 8 + nt * 2 + lhalf) ^ x7) << 4);
  const uint32_t pst0 = smb + SM_P + r0l * 128 + (lane & 3) * 4;
  const uint32_t pst1 = pst0 + 8 * 128;

  const int grow0 = q0 + r0l;

  float o[2][8][4];
#pragma unroll
  for (int mt = 0; mt < 2; mt++)
#pragma unroll
    for (int nt = 0; nt < 8; nt++)
#pragma unroll
      for (int e = 0; e < 4; e++) o[mt][nt][e] = 0.f;
  float lac0 = 0.f, lac1 = 0.f;

  for (int kt = 0; kt < NCH; kt++) {
    cp_wait1();       // K(kt) resident (V(kt) may still be in flight)
    __syncthreads();

    // hoisted bit-words (hidden under QK)
    const int wix = kt * 2 + kh;
    const uint32_t mword = g_maskbits[b * 32 + wix];
    const uint32_t dw0 = g_dropbits[(size_t)(b * kSQ + grow0) * 32 + wix];
    const uint32_t dw1 = g_dropbits[(size_t)(b * kSQ + grow0 + 8) * 32 + wix];

    // ---- QK: 16 rows x 32 keys per warp, k=256 ----
    float s[4][4];
#pragma unroll
    for (int t = 0; t < 4; t++) { s[t][0] = s[t][1] = s[t][2] = s[t][3] = 0.f; }

    const uint32_t kb0 = smb + SM_K + (kh * 32 + krow_off) * 512;
#pragma unroll
    for (int ds = 0; ds < 16; ds++) {
      uint32_t a[4], bb[8];
      ldsm4(a, qbase + ((((ds << 1) + lhalf) ^ x7) << 4));
      const uint32_t bo = (uint32_t)((((ds << 1) + kg_half) ^ x7k) << 4);
      ldsm4(bb, kb0 + bo);
      ldsm4(bb + 4, kb0 + 8192 + bo);
      mma16816(s[0], a, bb + 0);
      mma16816(s[1], a, bb + 2);
      mma16816(s[2], a, bb + 4);
      mma16816(s[3], a, bb + 6);
    }

    // ---- mask/exp2/dropout-select via bitwords; write P fp16 to smem ----
#pragma unroll
    for (int t = 0; t < 4; t++) {
      const int bp = t * 8 + colq;
      const bool m0 = (mword >> bp) & 1u, m1 = (mword >> (bp + 1)) & 1u;
      float p0 = m0 ? ex2(s[t][0]) : 0.f;
      float p1 = m1 ? ex2(s[t][1]) : 0.f;
      float p2 = m0 ? ex2(s[t][2]) : 0.f;
      float p3 = m1 ? ex2(s[t][3]) : 0.f;
      lac0 += p0 + p1;
      lac1 += p2 + p3;
      p0 = ((dw0 >> bp) & 1u) ? p0 : 0.f;          // keepinv folded into V
      p1 = ((dw0 >> (bp + 1)) & 1u) ? p1 : 0.f;
      p2 = ((dw1 >> bp) & 1u) ? p2 : 0.f;
      p3 = ((dw1 >> (bp + 1)) & 1u) ? p3 : 0.f;
      __half2 ha = __floats2half2_rn(p0, p1), hb = __floats2half2_rn(p2, p3);
      const int grp = kh * 4 + t;
      const uint32_t xo = (uint32_t)((grp ^ rowa) << 4);
      asm volatile("st.shared.b32 [%0], %1;" :: "r"(pst0 + xo), "r"(*reinterpret_cast<uint32_t*>(&ha)) : "memory");
      asm volatile("st.shared.b32 [%0], %1;" :: "r"(pst1 + xo), "r"(*reinterpret_cast<uint32_t*>(&hb)) : "memory");
    }
    __syncthreads();  // K consumed by all warps; P(kt) visible

    if (kt + 1 < NCH) {
      load_k(kt + 1);
      cp_commit();   // in flight: V(kt), K(kt+1)
      cp_wait1();    // V(kt) resident
    } else {
      cp_wait0();    // V(kt) resident (nothing else in flight)
    }
    __syncthreads();

    // ---- PV: 32 rows x 64 dv per warp ----
#pragma unroll
    for (int ks = 0; ks < 4; ks++) {
      uint32_t ap0[4], ap1[4];
      const uint32_t po = (uint32_t)((((ks << 1) + lhalf) ^ x7) << 4);
      ldsm4(ap0, pb0 + po);
      ldsm4(ap1, pb1 + po);
      const uint32_t vb = smb + SM_V + (ks * 16 + lq) * 512;
#pragma unroll
      for (int nt = 0; nt < 4; nt++) {
        uint32_t bb[4];
        ldsm4t(bb, vb + voff[nt]);
        mma16816(o[0][nt * 2 + 0], ap0, bb + 0);
        mma16816(o[0][nt * 2 + 1], ap0, bb + 2);
        mma16816(o[1][nt * 2 + 0], ap1, bb + 0);
        mma16816(o[1][nt * 2 + 1], ap1, bb + 2);
      }
    }
    __syncthreads();  // V consumed

    if (kt + 1 < NCH) { load_v(kt + 1); cp_commit(); }  // in flight: K(kt+1), V(kt+1)
  }

  // ---- l combine across key halves via smem ----
  lac0 += __shfl_xor_sync(0xffffffffu, lac0, 1);
  lac0 += __shfl_xor_sync(0xffffffffu, lac0, 2);
  lac1 += __shfl_xor_sync(0xffffffffu, lac1, 1);
  lac1 += __shfl_xor_sync(0xffffffffu, lac1, 2);
  if ((lane & 3) == 0) {
    asm volatile("st.shared.f32 [%0], %1;" :: "r"(smb + SM_L + (kh * 64 + r0l) * 4), "f"(lac0) : "memory");
    asm volatile("st.shared.f32 [%0], %1;" :: "r"(smb + SM_L + (kh * 64 + r0l + 8) * 4), "f"(lac1) : "memory");
  }
  __syncthreads();

#pragma unroll
  for (int mt = 0; mt < 2; mt++) {
    const int lr0 = pr * 32 + mt * 16 + rowa;
    float la0, lb0, la1, lb1;
    asm volatile("ld.shared.f32 %0, [%1];" : "=f"(la0) : "r"(smb + SM_L + lr0 * 4));
    asm volatile("ld.shared.f32 %0, [%1];" : "=f"(lb0) : "r"(smb + SM_L + (64 + lr0) * 4));
    asm volatile("ld.shared.f32 %0, [%1];" : "=f"(la1) : "r"(smb + SM_L + (lr0 + 8) * 4));
    asm volatile("ld.shared.f32 %0, [%1];" : "=f"(lb1) : "r"(smb + SM_L + (64 + lr0 + 8) * 4));
    const float inv0 = 1.0f / (la0 + lb0), inv1 = 1.0f / (la1 + lb1);
    float* o0 = out + ((size_t)b * kSQ + q0 + lr0) * kDV + pg * 64;
    float* o1 = o0 + (size_t)8 * kDV;
#pragma unroll
    for (int nt = 0; nt < 8; nt++) {
      const int c = nt * 8 + colq;
      float2 w0, w1;
      w0.x = o[mt][nt][0] * inv0;
      w0.y = o[mt][nt][1] * inv0;
      w1.x = o[mt][nt][2] * inv1;
      w1.y = o[mt][nt][3] * inv1;
      *reinterpret_cast<float2*>(o0 + c) = w0;
      *reinterpret_cast<float2*>(o1 + c) = w1;
    }
  }
}

extern "C" void kernel_launch(void* const* d_in, const int* in_sizes, int n_in,
                              void* d_out, int out_size) {
  const float* q = (const float*)d_in[0];
  const float* k = (const float*)d_in[1];
  const float* v = (const float*)d_in[2];
  const int* mask = (const int*)d_in[3];
  const float* du = (const float*)d_in[4];
  float* out = (float*)d_out;

  constexpr int nConv = (int)((size_t)kB * kSK * kD / 8 / 256);
  constexpr int nDrop = (int)((size_t)kB * kSQ * kSK / 1024 / 8);
  prep_fused<<<nConv + nDrop + 8, 256>>>(k, v, du, mask);

  cudaFuncSetAttribute(attn_hmma_kernel, cudaFuncAttributeMaxDynamicSharedMemorySize,
                       (int)SM_BYTES);
  attn_hmma_kernel<<<dim3(kSQ / BQ, kB), NT, SM_BYTES>>>(q, out);
}

// round 16
// speedup vs baseline: 1.0598x; 1.0390x over previous
#include <cuda_runtime.h>
#include <cuda_fp16.h>
#include <stdint.h>

namespace {
constexpr int kB = 64, kSQ = 1024, kSK = 1024, kD = 256, kDV = 256;
constexpr int BQ = 64, BKC = 64, NCH = kSK / BKC, NT = 512;
constexpr float kDropP = 0.1f;
constexpr float kKeepInv = 1.0f / 0.9f;                  // folded into V in prep
constexpr float kQScale = 0.0625f * 1.44269504088896f;   // scale * log2e

constexpr uint32_t SM_Q = 0;         // 64 x 512B = 32KB
constexpr uint32_t SM_K = 32768;     // 2 x 32KB = 64KB (double buffer)
constexpr uint32_t SM_V = 98304;     // 2 x 32KB = 64KB (double buffer)
constexpr uint32_t SM_P = 163840;    // 2 x 8KB = 16KB (double buffer)
constexpr uint32_t SM_L = 180224;    // float[2][64] = 512B
constexpr uint32_t SM_BYTES = 180736 + 1024;  // ~177.5KB -> 1 CTA/SM (RF-capped anyway)

__device__ __forceinline__ uint32_t swz(int row, int g) {  // 512B rows
  return (uint32_t)(row * 512 + ((g ^ (row & 7)) << 4));
}
__device__ __forceinline__ void cpa16(uint32_t d, const void* s) {
  asm volatile("cp.async.cg.shared.global [%0], [%1], 16;" :: "r"(d), "l"(s));
}
__device__ __forceinline__ void cp_commit() { asm volatile("cp.async.commit_group;" ::: "memory"); }
__device__ __forceinline__ void cp_wait1() { asm volatile("cp.async.wait_group 1;" ::: "memory"); }
__device__ __forceinline__ void cp_wait0() { asm volatile("cp.async.wait_group 0;" ::: "memory"); }

__device__ __forceinline__ void barg(int id, int cnt) {  // named barrier sync
  asm volatile("bar.sync %0, %1;" :: "r"(id), "r"(cnt) : "memory");
}
__device__ __forceinline__ void bara(int id, int cnt) {  // named barrier arrive
  asm volatile("bar.arrive %0, %1;" :: "r"(id), "r"(cnt) : "memory");
}
__device__ __forceinline__ float ex2(float x) {
  float r;
  asm("ex2.approx.f32 %0, %1;" : "=f"(r) : "f"(x));
  return r;
}
__device__ __forceinline__ void ldsm4(uint32_t* r, uint32_t a) {
  asm volatile("ldmatrix.sync.aligned.m8n8.x4.shared.b16 {%0,%1,%2,%3}, [%4];"
               : "=r"(r[0]), "=r"(r[1]), "=r"(r[2]), "=r"(r[3]) : "r"(a));
}
__device__ __forceinline__ void ldsm4t(uint32_t* r, uint32_t a) {
  asm volatile("ldmatrix.sync.aligned.m8n8.x4.trans.shared.b16 {%0,%1,%2,%3}, [%4];"
               : "=r"(r[0]), "=r"(r[1]), "=r"(r[2]), "=r"(r[3]) : "r"(a));
}
__device__ __forceinline__ void mma16816(float* d, const uint32_t* a, const uint32_t* b) {
  asm volatile(
      "mma.sync.aligned.m16n8k16.row.col.f32.f16.f16.f32 "
      "{%0,%1,%2,%3}, {%4,%5,%6,%7}, {%8,%9}, {%0,%1,%2,%3};"
      : "+f"(d[0]), "+f"(d[1]), "+f"(d[2]), "+f"(d[3])
      : "r"(a[0]), "r"(a[1]), "r"(a[2]), "r"(a[3]), "r"(b[0]), "r"(b[1]));
}
}  // namespace

__device__ __half g_Kh[(size_t)kB * kSK * kD];
__device__ __half g_Vh[(size_t)kB * kSK * kDV];   // V * keepinv
__device__ uint32_t g_dropbits[(size_t)kB * kSQ * (kSK / 32)];  // 8MB
__device__ uint32_t g_maskbits[kB * (kSK / 32)];                // 8KB

__global__ void prep_fused(const float* __restrict__ k, const float* __restrict__ v,
                           const float* __restrict__ du, const int* __restrict__ mask) {
  constexpr int nConv = (int)((size_t)kB * kSK * kD / 8 / 256);    // 8192
  constexpr int nDrop = (int)((size_t)kB * kSQ * kSK / 1024 / 8);  // 8192
  const int bx = blockIdx.x;
  if (bx < nConv) {
    const size_t base = ((size_t)bx * 256 + threadIdx.x) * 8;
    {
      float4 x0 = *reinterpret_cast<const float4*>(k + base);
      float4 x1 = *reinterpret_cast<const float4*>(k + base + 4);
      __half2* o = reinterpret_cast<__half2*>(g_Kh + base);
      o[0] = __floats2half2_rn(x0.x, x0.y);
      o[1] = __floats2half2_rn(x0.z, x0.w);
      o[2] = __floats2half2_rn(x1.x, x1.y);
      o[3] = __floats2half2_rn(x1.z, x1.w);
    }
    {
      float4 x0 = *reinterpret_cast<const float4*>(v + base);
      float4 x1 = *reinterpret_cast<const float4*>(v + base + 4);
      __half2* o = reinterpret_cast<__half2*>(g_Vh + base);
      o[0] = __floats2half2_rn(x0.x * kKeepInv, x0.y * kKeepInv);
      o[1] = __floats2half2_rn(x0.z * kKeepInv, x0.w * kKeepInv);
      o[2] = __floats2half2_rn(x1.x * kKeepInv, x1.y * kKeepInv);
      o[3] = __floats2half2_rn(x1.z * kKeepInv, x1.w * kKeepInv);
    }
  } else if (bx < nConv + nDrop) {
    const int lane = threadIdx.x & 31;
    const size_t warp = (((size_t)(bx - nConv) * 256) + threadIdx.x) >> 5;
    const size_t base = warp * 1024;
    uint32_t myword = 0;
#pragma unroll
    for (int i = 0; i < 32; i++) {
      const float u = du[base + (size_t)i * 32 + lane];
      const uint32_t bm = __ballot_sync(0xffffffffu, u >= kDropP);
      if (lane == i) myword = bm;
    }
    g_dropbits[warp * 32 + lane] = myword;
  } else {
    const int lane = threadIdx.x & 31;
    const int warp = (int)((((bx - nConv - nDrop) * 256) + threadIdx.x) >> 5);
    const size_t base = (size_t)warp * 1024;
    uint32_t myword = 0;
#pragma unroll
    for (int i = 0; i < 32; i++) {
      const int m = mask[base + (size_t)i * 32 + lane];
      const uint32_t bm = __ballot_sync(0xffffffffu, m != 0);
      if (lane == i) myword = bm;
    }
    g_maskbits[warp * 32 + lane] = myword;
  }
}

__global__ __launch_bounds__(NT, 1)
void attn_hmma_kernel(const float* __restrict__ q, float* __restrict__ out) {
  extern __shared__ char smraw[];
  uint32_t smb = (uint32_t)__cvta_generic_to_shared(smraw);
  smb = (smb + 1023u) & ~1023u;
  const int tid = threadIdx.x, wid = tid >> 5, lane = tid & 31;
  const int b = blockIdx.y, q0 = blockIdx.x * BQ;
  const bool isQK = (wid < 8);
  const int gt = tid & 255;  // thread id within group

  auto load_k = [&](int c, int buf) {
#pragma unroll
    for (int u = 0; u < 8; u++) {
      const int idx = gt + u * 256, row = idx >> 5, gr = idx & 31;
      cpa16(smb + SM_K + buf * 32768 + swz(row, gr),
            g_Kh + ((size_t)(b * kSK + c * BKC + row)) * kD + gr * 8);
    }
  };
  auto load_v = [&](int c, int buf) {
#pragma unroll
    for (int u = 0; u < 8; u++) {
      const int idx = gt + u * 256, row = idx >> 5, gr = idx & 31;
      cpa16(smb + SM_V + buf * 32768 + swz(row, gr),
            g_Vh + ((size_t)(b * kSK + c * BKC + row)) * kDV + gr * 8);
    }
  };

  if (isQK) {
    load_k(0, 0); cp_commit();
    load_k(1, 1); cp_commit();
  } else {
    load_v(0, 0); cp_commit();
    load_v(1, 1); cp_commit();
  }

  // ---- prologue: Q fp32 -> fp16 * (2^-4 * log2e), all 512 threads ----
#pragma unroll
  for (int u = 0; u < 4; u++) {
    const int idx = tid + u * NT, row = idx >> 5, gr = idx & 31;
    const float* src = q + ((size_t)(b * kSQ + q0 + row)) * kD + gr * 8;
    const float4 x0 = *reinterpret_cast<const float4*>(src);
    const float4 x1 = *reinterpret_cast<const float4*>(src + 4);
    __half2 h0 = __floats2half2_rn(x0.x * kQScale, x0.y * kQScale);
    __half2 h1 = __floats2half2_rn(x0.z * kQScale, x0.w * kQScale);
    __half2 h2 = __floats2half2_rn(x1.x * kQScale, x1.y * kQScale);
    __half2 h3 = __floats2half2_rn(x1.z * kQScale, x1.w * kQScale);
    asm volatile("st.shared.v4.b32 [%0], {%1,%2,%3,%4};"
                 :: "r"(smb + SM_Q + swz(row, gr)),
                    "r"(*reinterpret_cast<uint32_t*>(&h0)), "r"(*reinterpret_cast<uint32_t*>(&h1)),
                    "r"(*reinterpret_cast<uint32_t*>(&h2)), "r"(*reinterpret_cast<uint32_t*>(&h3))
                 : "memory");
  }
  __syncthreads();  // Q visible to QK group; groups diverge below

  // common lane constants
  const int lq = lane & 15, lhalf = lane >> 4;
  const int x7 = lq & 7;
  const int rowa = lane >> 2, colq = (lane & 3) * 2;

  if (isQK) {
    // ================= QK producer group (warps 0-7) =================
    const int g = wid & 3, kh = wid >> 2;
    const int x7k = lane & 7;
    const int r0l = g * 16 + rowa;
    const uint32_t qbase = smb + SM_Q + (g * 16 + lq) * 512;
    const int krow_off = (lane & 7) + ((lane >> 4) << 3);
    const int kg_half = (lane >> 3) & 1;
    const uint32_t pst0 = smb + SM_P + r0l * 128 + (lane & 3) * 4;
    const int grow0 = q0 + r0l;
    float lac0 = 0.f, lac1 = 0.f;

    for (int kt = 0; kt < NCH; kt++) {
      if (kt < NCH - 1) cp_wait1(); else cp_wait0();  // K(kt) resident
      barg(6, 256);                                    // visible to group

      const int wix = kt * 2 + kh;
      const uint32_t mword = g_maskbits[b * 32 + wix];
      const uint32_t dw0 = g_dropbits[(size_t)(b * kSQ + grow0) * 32 + wix];
      const uint32_t dw1 = g_dropbits[(size_t)(b * kSQ + grow0 + 8) * 32 + wix];

      float s[4][4];
#pragma unroll
      for (int t = 0; t < 4; t++) { s[t][0] = s[t][1] = s[t][2] = s[t][3] = 0.f; }

      const uint32_t kb0 = smb + SM_K + (kt & 1) * 32768 + (kh * 32 + krow_off) * 512;
#pragma unroll
      for (int ds = 0; ds < 16; ds++) {
        uint32_t a[4], bb[8];
        ldsm4(a, qbase + ((((ds << 1) + lhalf) ^ x7) << 4));
        const uint32_t bo = (uint32_t)((((ds << 1) + kg_half) ^ x7k) << 4);
        ldsm4(bb, kb0 + bo);
        ldsm4(bb + 4, kb0 + 8192 + bo);
        mma16816(s[0], a, bb + 0);
        mma16816(s[1], a, bb + 2);
        mma16816(s[2], a, bb + 4);
        mma16816(s[3], a, bb + 6);
      }

      barg(6, 256);  // all QK warps done reading K(kt) -> buffer reusable
      if (kt + 2 < NCH) { load_k(kt + 2, kt & 1); cp_commit(); }
      if (kt >= 2) barg(4 + (kt & 1), NT);  // P buffer (kt&1) consumed by PV

      const uint32_t poff = (uint32_t)((kt & 1) * 8192);
#pragma unroll
      for (int t = 0; t < 4; t++) {
        const int bp = t * 8 + colq;
        const bool m0 = (mword >> bp) & 1u, m1 = (mword >> (bp + 1)) & 1u;
        float p0 = m0 ? ex2(s[t][0]) : 0.f;
        float p1 = m1 ? ex2(s[t][1]) : 0.f;
        float p2 = m0 ? ex2(s[t][2]) : 0.f;
        float p3 = m1 ? ex2(s[t][3]) : 0.f;
        lac0 += p0 + p1;
        lac1 += p2 + p3;
        p0 = ((dw0 >> bp) & 1u) ? p0 : 0.f;
        p1 = ((dw0 >> (bp + 1)) & 1u) ? p1 : 0.f;
        p2 = ((dw1 >> bp) & 1u) ? p2 : 0.f;
        p3 = ((dw1 >> (bp + 1)) & 1u) ? p3 : 0.f;
        __half2 ha = __floats2half2_rn(p0, p1), hb = __floats2half2_rn(p2, p3);
        const int grp = kh * 4 + t;
        const uint32_t xo = (uint32_t)((grp ^ rowa) << 4) + poff;
        asm volatile("st.shared.b32 [%0], %1;" :: "r"(pst0 + xo),
                     "r"(*reinterpret_cast<uint32_t*>(&ha)) : "memory");
        asm volatile("st.shared.b32 [%0], %1;" :: "r"(pst0 + 1024 + xo),
                     "r"(*reinterpret_cast<uint32_t*>(&hb)) : "memory");
      }
      bara(2 + (kt & 1), NT);  // P(kt) ready
    }

    // l combine across key halves
    lac0 += __shfl_xor_sync(0xffffffffu, lac0, 1);
    lac0 += __shfl_xor_sync(0xffffffffu, lac0, 2);
    lac1 += __shfl_xor_sync(0xffffffffu, lac1, 1);
    lac1 += __shfl_xor_sync(0xffffffffu, lac1, 2);
    if ((lane & 3) == 0) {
      asm volatile("st.shared.f32 [%0], %1;" :: "r"(smb + SM_L + (kh * 64 + r0l) * 4), "f"(lac0) : "memory");
      asm volatile("st.shared.f32 [%0], %1;" :: "r"(smb + SM_L + (kh * 64 + r0l + 8) * 4), "f"(lac1) : "memory");
    }
    __syncthreads();
  } else {
    // ================= PV consumer group (warps 8-15) =================
    const int pwid = wid - 8;
    const int pr = pwid >> 2, pg = pwid & 3;
    const uint32_t pb0 = smb + SM_P + (pr * 32 + lq) * 128;
    const uint32_t pb1 = pb0 + 16 * 128;
    uint32_t voff[4];
#pragma unroll
    for (int nt = 0; nt < 4; nt++) voff[nt] = (uint32_t)(((pg * 8 + nt * 2 + lhalf) ^ x7) << 4);

    float o[2][8][4];
#pragma unroll
    for (int mt = 0; mt < 2; mt++)
#pragma unroll
      for (int nt = 0; nt < 8; nt++)
#pragma unroll
        for (int e = 0; e < 4; e++) o[mt][nt][e] = 0.f;

    for (int kt = 0; kt < NCH; kt++) {
      if (kt < NCH - 1) cp_wait1(); else cp_wait0();  // V(kt) resident
      barg(7, 256);                                    // visible to group
      barg(2 + (kt & 1), NT);                          // P(kt) ready

      const uint32_t poff = (uint32_t)((kt & 1) * 8192);
      const uint32_t vbase = smb + SM_V + (kt & 1) * 32768;
#pragma unroll
      for (int ks = 0; ks < 4; ks++) {
        uint32_t ap0[4], ap1[4];
        const uint32_t po = ((uint32_t)((((ks << 1) + lhalf) ^ x7) << 4)) + poff;
        ldsm4(ap0, pb0 + po);
        ldsm4(ap1, pb1 + po);
        const uint32_t vb = vbase + (ks * 16 + lq) * 512;
#pragma unroll
        for (int nt = 0; nt < 4; nt++) {
          uint32_t bb[4];
          ldsm4t(bb, vb + voff[nt]);
          mma16816(o[0][nt * 2 + 0], ap0, bb + 0);
          mma16816(o[0][nt * 2 + 1], ap0, bb + 2);
          mma16816(o[1][nt * 2 + 0], ap1, bb + 0);
          mma16816(o[1][nt * 2 + 1], ap1, bb + 2);
        }
      }
      bara(4 + (kt & 1), NT);  // P(kt) consumed
      barg(7, 256);            // all PV warps done with V(kt)
      if (kt + 2 < NCH) { load_v(kt + 2, kt & 1); cp_commit(); }
    }

    __syncthreads();  // l values from QK group visible

#pragma unroll
    for (int mt = 0; mt < 2; mt++) {
      const int lr0 = pr * 32 + mt * 16 + rowa;
      float la0, lb0, la1, lb1;
      asm volatile("ld.shared.f32 %0, [%1];" : "=f"(la0) : "r"(smb + SM_L + lr0 * 4));
      asm volatile("ld.shared.f32 %0, [%1];" : "=f"(lb0) : "r"(smb + SM_L + (64 + lr0) * 4));
      asm volatile("ld.shared.f32 %0, [%1];" : "=f"(la1) : "r"(smb + SM_L + (lr0 + 8) * 4));
      asm volatile("ld.shared.f32 %0, [%1];" : "=f"(lb1) : "r"(smb + SM_L + (64 + lr0 + 8) * 4));
      const float inv0 = 1.0f / (la0 + lb0), inv1 = 1.0f / (la1 + lb1);
      float* o0 = out + ((size_t)b * kSQ + q0 + lr0) * kDV + pg * 64;
      float* o1 = o0 + (size_t)8 * kDV;
#pragma unroll
      for (int nt = 0; nt < 8; nt++) {
        const int c = nt * 8 + colq;
        float2 w0, w1;
        w0.x = o[mt][nt][0] * inv0;
        w0.y = o[mt][nt][1] * inv0;
        w1.x = o[mt][nt][2] * inv1;
        w1.y = o[mt][nt][3] * inv1;
        *reinterpret_cast<float2*>(o0 + c) = w0;
        *reinterpret_cast<float2*>(o1 + c) = w1;
      }
    }
  }
}

extern "C" void kernel_launch(void* const* d_in, const int* in_sizes, int n_in,
                              void* d_out, int out_size) {
  const float* q = (const float*)d_in[0];
  const float* k = (const float*)d_in[1];
  const float* v = (const float*)d_in[2];
  const int* mask = (const int*)d_in[3];
  const float* du = (const float*)d_in[4];
  float* out = (float*)d_out;

  constexpr int nConv = (int)((size_t)kB * kSK * kD / 8 / 256);
  constexpr int nDrop = (int)((size_t)kB * kSQ * kSK / 1024 / 8);
  prep_fused<<<nConv + nDrop + 8, 256>>>(k, v, du, mask);

  cudaFuncSetAttribute(attn_hmma_kernel, cudaFuncAttributeMaxDynamicSharedMemorySize,
                       (int)SM_BYTES);
  attn_hmma_kernel<<<dim3(kSQ / BQ, kB), NT, SM_BYTES>>>(q, out);
}